// round 5
// baseline (speedup 1.0000x reference)
#include <cuda_runtime.h>

// GACRF, two-kernel barrier-free split.
//   K1: softmax(C=19) + encode(G=8)  -> Qg scratch [b,8,H,W]   (pure stream)
//   K2: 3x3 dynamic filter on Qg + decode(E^T) + logit - *     (stream, Qg via L2/L1)
//
// Rationale (R4): fused kernel was stall-bound on serial DRAM trips separated
// by __syncthreads with only 2 CTAs/SM (all pipes <35%). Split removes every
// intra-CTA barrier; Qg (33.5MB) fits in L2 so K2's 9x-reuse neighbor reads are
// cache hits, not DRAM.
//
// Shapes (fixed): b=4, C=19, G=8, H=W=512.

#define BATCH 4
#define NC 19
#define NG 8
#define IMH 512
#define IMW 512
#define HW (IMH * IMW)
#define NTHREADS 256

// scratch: 4*8*512*512 floats = 33.5 MB (device global array: allowed)
__device__ float g_Qg[(size_t)BATCH * NG * HW];

__device__ __forceinline__ void load_E(const float* __restrict__ matrix,
                                       float Esh[NG][NC]) {
    const int tid = threadIdx.x;
    if (tid < NC) {
        const int c = tid;
        float m[NG];
        float mx = -1e30f;
        #pragma unroll
        for (int g = 0; g < NG; g++) {
            m[g] = 100.0f * matrix[g * NC + c];
            mx = fmaxf(mx, m[g]);
        }
        float s = 0.0f;
        #pragma unroll
        for (int g = 0; g < NG; g++) { m[g] = __expf(m[g] - mx); s += m[g]; }
        const float r = 1.0f / s;
        #pragma unroll
        for (int g = 0; g < NG; g++) Esh[g][c] = m[g] * r;
    }
    __syncthreads();
}

// ---------------- K1: softmax + encode, 4 pixels/thread ----------------
__global__ __launch_bounds__(NTHREADS) void k_encode(
    const float* __restrict__ logit,   // [b,C,H,W]
    const float* __restrict__ matrix)  // [G,C]
{
    __shared__ float Esh[NG][NC];
    load_E(matrix, Esh);

    const int idx = blockIdx.x * NTHREADS + threadIdx.x;   // 0 .. 262143
    const int b   = idx >> 16;                             // 65536 groups / image
    const int p4  = (idx & 65535) << 2;                    // pixel base (16B aligned)

    const float* __restrict__ lp = logit + (size_t)b * NC * HW + p4;

    float4 acc[NG];
    #pragma unroll
    for (int g = 0; g < NG; g++) acc[g] = make_float4(0.f, 0.f, 0.f, 0.f);
    float4 s = make_float4(0.f, 0.f, 0.f, 0.f);

    #pragma unroll
    for (int c = 0; c < NC; c++) {
        const float4 v = __ldg((const float4*)(lp + (size_t)c * HW));
        const float e0 = __expf(v.x), e1 = __expf(v.y);
        const float e2 = __expf(v.z), e3 = __expf(v.w);
        s.x += e0; s.y += e1; s.z += e2; s.w += e3;
        #pragma unroll
        for (int g = 0; g < NG; g++) {
            const float E = Esh[g][c];
            acc[g].x = fmaf(E, e0, acc[g].x);
            acc[g].y = fmaf(E, e1, acc[g].y);
            acc[g].z = fmaf(E, e2, acc[g].z);
            acc[g].w = fmaf(E, e3, acc[g].w);
        }
    }
    const float r0 = __frcp_rn(s.x), r1 = __frcp_rn(s.y);
    const float r2 = __frcp_rn(s.z), r3 = __frcp_rn(s.w);

    float* __restrict__ qp = g_Qg + (size_t)b * NG * HW + p4;
    #pragma unroll
    for (int g = 0; g < NG; g++) {
        float4 o;
        o.x = acc[g].x * r0; o.y = acc[g].y * r1;
        o.z = acc[g].z * r2; o.w = acc[g].w * r3;
        *(float4*)(qp + (size_t)g * HW) = o;
    }
}

// ------------- K2: 3x3 filter + decode + subtract, 4 px/thread -------------
__global__ __launch_bounds__(NTHREADS) void k_filter(
    const float* __restrict__ Fk,      // [b,9,H,W]
    const float* __restrict__ logit,   // [b,C,H,W]
    const float* __restrict__ matrix,  // [G,C]
    float* __restrict__ out)           // [b,C,H,W]
{
    __shared__ float Esh[NG][NC];
    load_E(matrix, Esh);

    const int idx = blockIdx.x * NTHREADS + threadIdx.x;   // 0 .. 262143
    const int b   = idx >> 16;
    const int p4  = (idx & 65535) << 2;
    const int y   = p4 >> 9;            // 0..511
    const int x   = p4 & 511;           // 0,4,...,508

    // 9 per-pixel filter taps (aligned float4)
    float4 f4[9];
    {
        const float* __restrict__ fp = Fk + (size_t)b * 9 * HW + p4;
        #pragma unroll
        for (int k = 0; k < 9; k++) f4[k] = __ldg((const float4*)(fp + (size_t)k * HW));
    }

    // filter Qg (global, L2/L1-resident) with image-border guards
    float4 filt[NG];
    #pragma unroll
    for (int g = 0; g < NG; g++) filt[g] = make_float4(0.f, 0.f, 0.f, 0.f);

    const float* __restrict__ qb = g_Qg + (size_t)b * NG * HW;
    const bool has_l = (x > 0);
    const bool has_r = (x < IMW - 4);

    #pragma unroll
    for (int dr = 0; dr < 3; dr++) {
        const int ry = y + dr - 1;
        if ((unsigned)ry >= IMH) continue;     // zero-padded rows
        const float4 fa = f4[dr * 3 + 0];
        const float4 fb = f4[dr * 3 + 1];
        const float4 fc = f4[dr * 3 + 2];
        const float* __restrict__ qrow0 = qb + (size_t)ry * IMW + x;
        #pragma unroll
        for (int g = 0; g < NG; g++) {
            const float* __restrict__ qrow = qrow0 + (size_t)g * HW;
            const float4 qm = __ldg((const float4*)qrow);
            const float  q0 = has_l ? __ldg(qrow - 1) : 0.f;
            const float  q5 = has_r ? __ldg(qrow + 4) : 0.f;
            filt[g].x = fmaf(fa.x, q0,   fmaf(fb.x, qm.x, fmaf(fc.x, qm.y, filt[g].x)));
            filt[g].y = fmaf(fa.y, qm.x, fmaf(fb.y, qm.y, fmaf(fc.y, qm.z, filt[g].y)));
            filt[g].z = fmaf(fa.z, qm.y, fmaf(fb.z, qm.z, fmaf(fc.z, qm.w, filt[g].z)));
            filt[g].w = fmaf(fa.w, qm.z, fmaf(fb.w, qm.w, fmaf(fc.w, q5,   filt[g].w)));
        }
    }

    // decode (E^T) + subtract + store
    const float* __restrict__ lp = logit + (size_t)b * NC * HW + p4;
    float* __restrict__       op = out   + (size_t)b * NC * HW + p4;
    #pragma unroll
    for (int c = 0; c < NC; c++) {
        float4 a = make_float4(0.f, 0.f, 0.f, 0.f);
        #pragma unroll
        for (int g = 0; g < NG; g++) {
            const float E = Esh[g][c];
            a.x = fmaf(E, filt[g].x, a.x);
            a.y = fmaf(E, filt[g].y, a.y);
            a.z = fmaf(E, filt[g].z, a.z);
            a.w = fmaf(E, filt[g].w, a.w);
        }
        const float4 l4 = __ldg((const float4*)(lp + (size_t)c * HW));
        float4 o;
        o.x = l4.x - a.x; o.y = l4.y - a.y;
        o.z = l4.z - a.z; o.w = l4.w - a.w;
        *(float4*)(op + (size_t)c * HW) = o;
    }
}

extern "C" void kernel_launch(void* const* d_in, const int* in_sizes, int n_in,
                              void* d_out, int out_size) {
    // Bind inputs by element count (robust to ordering):
    //   F: 9437184, logit: 19922944, matrix: 152
    const float* F      = nullptr;
    const float* logit  = nullptr;
    const float* matrix = nullptr;
    for (int i = 0; i < n_in; i++) {
        if (in_sizes[i] == 9437184)       F      = (const float*)d_in[i];
        else if (in_sizes[i] == 19922944) logit  = (const float*)d_in[i];
        else if (in_sizes[i] == 152)      matrix = (const float*)d_in[i];
    }
    float* out = (float*)d_out;

    const int ngroups = BATCH * HW / 4;         // 262144
    const int nblk    = ngroups / NTHREADS;     // 1024
    k_encode<<<nblk, NTHREADS>>>(logit, matrix);
    k_filter<<<nblk, NTHREADS>>>(F, logit, matrix, out);
}

// round 6
// speedup vs baseline: 1.4451x; 1.4451x over previous
#include <cuda_runtime.h>

// GACRF fused: softmax(C=19) -> encode(G=8) -> 3x3 dynamic filter -> decode ->
// logit - result.  Single kernel, 64x16 tile + 1px halo in smem.
//
// R5: balanced single-pass phase 1. The R3 version striped 324 halo-tile work
// items over 256 threads, so 3 of 8 warps ran a second full softmax pass and
// the barrier charged it to the whole CTA. Now 162 threads each take TWO
// adjacent 4-px groups in ONE deep pass (38 batched float4 loads). Tile edges
// are 4-aligned so halo groups are always fully in- or out-of-image: one
// uniform vector path, OOB groups just store zeros.
//
// Shapes (fixed): b=4, C=19, G=8, H=W=512, K=3.

#define BATCH 4
#define NC 19
#define NG 8
#define IMH 512
#define IMW 512
#define HW (IMH * IMW)

#define TW 64            // output tile width
#define TH 16            // output tile height
#define EH (TH + 2)      // 18 extended rows (global y0-1 .. y0+16)
#define EWP 72           // padded extended width, covers global [x0-4, x0+68)
#define NPAIR (EH * 9)   // 162 phase-1 threads, each: 2 adjacent 4-px groups
#define NTHREADS 256

__global__ __launch_bounds__(NTHREADS, 2) void gacrf_fused_kernel(
    const float* __restrict__ Fk,     // [b,9,H,W]
    const float* __restrict__ logit,  // [b,C,H,W]
    const float* __restrict__ matrix, // [G,C]
    float* __restrict__ out)          // [b,C,H,W]
{
    __shared__ float Esh[NG][NC];
    __shared__ __align__(16) float Qg[NG][EH][EWP];   // 41472 B

    const int tid = threadIdx.x;
    const int bx = blockIdx.x, by = blockIdx.y, bz = blockIdx.z;

    // ---- E = softmax over G of 100*matrix ----
    if (tid < NC) {
        const int c = tid;
        float m[NG];
        float mx = -1e30f;
        #pragma unroll
        for (int g = 0; g < NG; g++) {
            m[g] = 100.0f * matrix[g * NC + c];
            mx = fmaxf(mx, m[g]);
        }
        float s = 0.0f;
        #pragma unroll
        for (int g = 0; g < NG; g++) { m[g] = __expf(m[g] - mx); s += m[g]; }
        const float r = 1.0f / s;
        #pragma unroll
        for (int g = 0; g < NG; g++) Esh[g][c] = m[g] * r;
    }
    __syncthreads();

    const int x0 = bx * TW;
    const int y0 = by * TH;
    const float* __restrict__ logit_b = logit + (size_t)bz * NC * HW;

    // ---- Phase 1: softmax+encode, ONE pass, 8 px (2 groups) per thread ----
    // ext col e <-> global x0 - 4 + e ; ext row r <-> global y0 - 1 + r
    if (tid < NPAIR) {
        const int r   = tid / 9;
        const int j   = tid - r * 9;          // pair index 0..8
        const int gy  = y0 + r - 1;
        const int gxb = x0 - 4 + 8 * j;       // group A cols gxb.., B gxb+4..

        // groups are 4-aligned vs the 512 image: fully inside or fully outside
        const bool rowok = (unsigned)gy < IMH;
        const bool vA = rowok && ((unsigned)gxb       < IMW);
        const bool vB = rowok && ((unsigned)(gxb + 4) < IMW);

        float4 aA[NG], aB[NG];
        #pragma unroll
        for (int g = 0; g < NG; g++) {
            aA[g] = make_float4(0.f, 0.f, 0.f, 0.f);
            aB[g] = make_float4(0.f, 0.f, 0.f, 0.f);
        }
        float4 sA = make_float4(0.f, 0.f, 0.f, 0.f);
        float4 sB = make_float4(0.f, 0.f, 0.f, 0.f);

        const float* __restrict__ p = logit_b + (size_t)gy * IMW + gxb;
        const float4 z4 = make_float4(0.f, 0.f, 0.f, 0.f);

        #pragma unroll
        for (int c = 0; c < NC; c++) {
            const float4 vA4 = vA ? __ldg((const float4*)(p + (size_t)c * HW))     : z4;
            const float4 vB4 = vB ? __ldg((const float4*)(p + (size_t)c * HW + 4)) : z4;
            const float ea0 = __expf(vA4.x), ea1 = __expf(vA4.y);
            const float ea2 = __expf(vA4.z), ea3 = __expf(vA4.w);
            const float eb0 = __expf(vB4.x), eb1 = __expf(vB4.y);
            const float eb2 = __expf(vB4.z), eb3 = __expf(vB4.w);
            sA.x += ea0; sA.y += ea1; sA.z += ea2; sA.w += ea3;
            sB.x += eb0; sB.y += eb1; sB.z += eb2; sB.w += eb3;
            #pragma unroll
            for (int g = 0; g < NG; g++) {
                const float E = Esh[g][c];
                aA[g].x = fmaf(E, ea0, aA[g].x);
                aA[g].y = fmaf(E, ea1, aA[g].y);
                aA[g].z = fmaf(E, ea2, aA[g].z);
                aA[g].w = fmaf(E, ea3, aA[g].w);
                aB[g].x = fmaf(E, eb0, aB[g].x);
                aB[g].y = fmaf(E, eb1, aB[g].y);
                aB[g].z = fmaf(E, eb2, aB[g].z);
                aB[g].w = fmaf(E, eb3, aB[g].w);
            }
        }
        const float ra0 = __frcp_rn(sA.x), ra1 = __frcp_rn(sA.y);
        const float ra2 = __frcp_rn(sA.z), ra3 = __frcp_rn(sA.w);
        const float rb0 = __frcp_rn(sB.x), rb1 = __frcp_rn(sB.y);
        const float rb2 = __frcp_rn(sB.z), rb3 = __frcp_rn(sB.w);

        #pragma unroll
        for (int g = 0; g < NG; g++) {
            float4 oA = z4, oB = z4;
            if (vA) { oA.x = aA[g].x * ra0; oA.y = aA[g].y * ra1;
                      oA.z = aA[g].z * ra2; oA.w = aA[g].w * ra3; }
            if (vB) { oB.x = aB[g].x * rb0; oB.y = aB[g].y * rb1;
                      oB.z = aB[g].z * rb2; oB.w = aB[g].w * rb3; }
            *(float4*)&Qg[g][r][8 * j]     = oA;
            *(float4*)&Qg[g][r][8 * j + 4] = oB;
        }
    }
    __syncthreads();

    // ---- Phase 2: 3x3 filter + decode + subtract, 4 px/thread ----
    {
        const int y  = tid >> 4;           // 0..15
        const int xg = (tid & 15) << 2;    // 0,4,..,60
        const int gy = y0 + y;

        const float* __restrict__ F_b = Fk + (size_t)bz * 9 * HW;
        float* __restrict__ out_b     = out + (size_t)bz * NC * HW;

        // 9 per-pixel filter taps (streaming: no reuse -> ldcs)
        float4 f4[9];
        const float* __restrict__ fp = F_b + (size_t)gy * IMW + (x0 + xg);
        #pragma unroll
        for (int k = 0; k < 9; k++) f4[k] = __ldcs((const float4*)(fp + (size_t)k * HW));

        float4 filt[NG];
        #pragma unroll
        for (int g = 0; g < NG; g++) filt[g] = make_float4(0.f, 0.f, 0.f, 0.f);

        #pragma unroll
        for (int g = 0; g < NG; g++) {
            #pragma unroll
            for (int dr = 0; dr < 3; dr++) {
                const float* __restrict__ qrow = &Qg[g][y + dr][xg + 3];
                const float  q0 = qrow[0];
                const float4 qm = *(const float4*)(qrow + 1);
                const float  q5 = qrow[5];
                const float4 fa = f4[dr * 3 + 0];
                const float4 fb = f4[dr * 3 + 1];
                const float4 fc = f4[dr * 3 + 2];
                filt[g].x = fmaf(fa.x, q0,   fmaf(fb.x, qm.x, fmaf(fc.x, qm.y, filt[g].x)));
                filt[g].y = fmaf(fa.y, qm.x, fmaf(fb.y, qm.y, fmaf(fc.y, qm.z, filt[g].y)));
                filt[g].z = fmaf(fa.z, qm.y, fmaf(fb.z, qm.z, fmaf(fc.z, qm.w, filt[g].z)));
                filt[g].w = fmaf(fa.w, qm.z, fmaf(fb.w, qm.w, fmaf(fc.w, q5,   filt[g].w)));
            }
        }

        const float* __restrict__ lp = logit_b + (size_t)gy * IMW + (x0 + xg);
        float* __restrict__       op = out_b   + (size_t)gy * IMW + (x0 + xg);
        #pragma unroll
        for (int c = 0; c < NC; c++) {
            float4 a = make_float4(0.f, 0.f, 0.f, 0.f);
            #pragma unroll
            for (int g = 0; g < NG; g++) {
                const float E = Esh[g][c];
                a.x = fmaf(E, filt[g].x, a.x);
                a.y = fmaf(E, filt[g].y, a.y);
                a.z = fmaf(E, filt[g].z, a.z);
                a.w = fmaf(E, filt[g].w, a.w);
            }
            const float4 l4 = __ldg((const float4*)(lp + (size_t)c * HW));
            float4 o;
            o.x = l4.x - a.x; o.y = l4.y - a.y;
            o.z = l4.z - a.z; o.w = l4.w - a.w;
            __stcs((float4*)(op + (size_t)c * HW), o);   // streaming store
        }
    }
}

extern "C" void kernel_launch(void* const* d_in, const int* in_sizes, int n_in,
                              void* d_out, int out_size) {
    // Bind inputs by element count (robust to ordering):
    //   F: 9437184, logit: 19922944, matrix: 152
    const float* F      = nullptr;
    const float* logit  = nullptr;
    const float* matrix = nullptr;
    for (int i = 0; i < n_in; i++) {
        if (in_sizes[i] == 9437184)       F      = (const float*)d_in[i];
        else if (in_sizes[i] == 19922944) logit  = (const float*)d_in[i];
        else if (in_sizes[i] == 152)      matrix = (const float*)d_in[i];
    }
    float* out = (float*)d_out;

    dim3 grid(IMW / TW, IMH / TH, BATCH);   // (8, 32, 4)
    gacrf_fused_kernel<<<grid, NTHREADS>>>(F, logit, matrix, out);
}